// round 3
// baseline (speedup 1.0000x reference)
#include <cuda_runtime.h>
#include <math.h>

// Problem constants
#define D_MODEL 1024
#define N_HEADS 16
#define D_HEAD  64
#define BATCH   4
#define SEQ     512
#define M_TOK   (BATCH * SEQ)       // 2048
#define QKV_N   (3 * D_MODEL)       // 3072
#define BHN     (BATCH * N_HEADS)   // 64

// ---------------- device scratch (no runtime allocation allowed) ----------------
__device__ float g_rope_cos[SEQ * D_HEAD];
__device__ float g_rope_sin[SEQ * D_HEAD];
__device__ float g_qkv_r[(size_t)M_TOK * QKV_N];
__device__ float g_qkv_i[(size_t)M_TOK * QKV_N];
__device__ float g_Qr[(size_t)BHN * SEQ * D_HEAD];
__device__ float g_Qi[(size_t)BHN * SEQ * D_HEAD];
__device__ float g_Kr[(size_t)BHN * SEQ * D_HEAD];
__device__ float g_Ki[(size_t)BHN * SEQ * D_HEAD];
__device__ float g_Vr[(size_t)BHN * SEQ * D_HEAD];
__device__ float g_Vi[(size_t)BHN * SEQ * D_HEAD];
__device__ float g_att_r[(size_t)M_TOK * D_MODEL];
__device__ float g_att_i[(size_t)M_TOK * D_MODEL];

// ---------------- kernel 1: RoPE rotor table ----------------
__global__ void rope_table_kernel() {
    int i = blockIdx.x * blockDim.x + threadIdx.x;
    if (i >= SEQ * D_HEAD) return;
    int s = i / D_HEAD;
    int d = i % D_HEAD;
    float inv_freq = powf(10000.0f, -(float)d / (float)D_HEAD);
    float ang = (float)s * inv_freq;
    float sn, cs;
    sincosf(ang, &sn, &cs);
    g_rope_cos[i] = cs;
    g_rope_sin[i] = sn;
}

// ---------------- kernel 2: complex GEMM  C = A @ B^T (complex, no conj) ----------------
// A: [M,K] row-major (re,im), B: [N,K] row-major (re,im), C: [M,N] row-major.
// Tile 64x64, BK=16, 256 threads, 4x4 register tile per thread.
// Thread (ty,tx): rows m0 + ty*4+i, cols n0 + tx + 16*j  (contiguous lanes over n).
__global__ __launch_bounds__(256, 3) void cgemm_kernel(
    const float* __restrict__ Are, const float* __restrict__ Aim,
    const float* __restrict__ Bre, const float* __restrict__ Bim,
    float* __restrict__ Cre, float* __restrict__ Cim,
    int M, int N, int K)
{
    // transposed smem tiles [k][row] with pitch 65 (conflict-free inner reads)
    __shared__ float As_re[16 * 65];
    __shared__ float As_im[16 * 65];
    __shared__ float Bs_re[16 * 65];
    __shared__ float Bs_im[16 * 65];

    const int t  = threadIdx.x;
    const int ty = t >> 4;      // 0..15
    const int tx = t & 15;      // 0..15
    const int m0 = blockIdx.y * 64;
    const int n0 = blockIdx.x * 64;

    const int lm = t >> 2;      // 0..63 : row within tile
    const int lf = t & 3;       // 0..3  : float4 index within 16-wide k slice

    float c_re[16];
    float c_im[16];
#pragma unroll
    for (int q = 0; q < 16; q++) { c_re[q] = 0.0f; c_im[q] = 0.0f; }

    const float* pAre = Are + (size_t)(m0 + lm) * K + lf * 4;
    const float* pAim = Aim + (size_t)(m0 + lm) * K + lf * 4;
    const float* pBre = Bre + (size_t)(n0 + lm) * K + lf * 4;
    const float* pBim = Bim + (size_t)(n0 + lm) * K + lf * 4;

    for (int k0 = 0; k0 < K; k0 += 16) {
        float4 ar = *(const float4*)(pAre + k0);
        float4 ai = *(const float4*)(pAim + k0);
        float4 br = *(const float4*)(pBre + k0);
        float4 bi = *(const float4*)(pBim + k0);

        __syncthreads();   // previous iteration's reads done before overwrite

        int kb = lf * 4;
        As_re[(kb + 0) * 65 + lm] = ar.x;
        As_re[(kb + 1) * 65 + lm] = ar.y;
        As_re[(kb + 2) * 65 + lm] = ar.z;
        As_re[(kb + 3) * 65 + lm] = ar.w;
        As_im[(kb + 0) * 65 + lm] = ai.x;
        As_im[(kb + 1) * 65 + lm] = ai.y;
        As_im[(kb + 2) * 65 + lm] = ai.z;
        As_im[(kb + 3) * 65 + lm] = ai.w;
        Bs_re[(kb + 0) * 65 + lm] = br.x;
        Bs_re[(kb + 1) * 65 + lm] = br.y;
        Bs_re[(kb + 2) * 65 + lm] = br.z;
        Bs_re[(kb + 3) * 65 + lm] = br.w;
        Bs_im[(kb + 0) * 65 + lm] = bi.x;
        Bs_im[(kb + 1) * 65 + lm] = bi.y;
        Bs_im[(kb + 2) * 65 + lm] = bi.z;
        Bs_im[(kb + 3) * 65 + lm] = bi.w;

        __syncthreads();

#pragma unroll
        for (int kk = 0; kk < 16; kk++) {
            float a_r[4], a_i[4], b_r[4], b_i[4];
#pragma unroll
            for (int i = 0; i < 4; i++) {
                a_r[i] = As_re[kk * 65 + ty * 4 + i];
                a_i[i] = As_im[kk * 65 + ty * 4 + i];
            }
#pragma unroll
            for (int j = 0; j < 4; j++) {
                b_r[j] = Bs_re[kk * 65 + tx + 16 * j];
                b_i[j] = Bs_im[kk * 65 + tx + 16 * j];
            }
#pragma unroll
            for (int i = 0; i < 4; i++)
#pragma unroll
                for (int j = 0; j < 4; j++) {
                    c_re[i * 4 + j] += a_r[i] * b_r[j] - a_i[i] * b_i[j];
                    c_im[i * 4 + j] += a_r[i] * b_i[j] + a_i[i] * b_r[j];
                }
        }
    }

#pragma unroll
    for (int i = 0; i < 4; i++) {
        size_t row = (size_t)(m0 + ty * 4 + i) * N;
#pragma unroll
        for (int j = 0; j < 4; j++) {
            int col = n0 + tx + 16 * j;
            Cre[row + col] = c_re[i * 4 + j];
            Cim[row + col] = c_im[i * 4 + j];
        }
    }
}

// ---------------- kernel 3: RoPE apply + split heads ----------------
// qkv [B,S,3D] -> Q/K/V in [B*H, S, Dh] with RoPE on Q,K (complex rotor multiply).
__global__ void rope_apply_kernel() {
    int i = blockIdx.x * blockDim.x + threadIdx.x;
    if (i >= BHN * SEQ * D_HEAD) return;
    int d = i & 63;
    int s = (i >> 6) & 511;
    int h = (i >> 15) & 15;
    int b = i >> 19;

    size_t base = (size_t)(b * SEQ + s) * QKV_N + h * D_HEAD + d;
    float qr = g_qkv_r[base];
    float qi = g_qkv_i[base];
    float kr = g_qkv_r[base + D_MODEL];
    float ki = g_qkv_i[base + D_MODEL];
    float vr = g_qkv_r[base + 2 * D_MODEL];
    float vi = g_qkv_i[base + 2 * D_MODEL];

    float cs = g_rope_cos[s * D_HEAD + d];
    float sn = g_rope_sin[s * D_HEAD + d];

    g_Qr[i] = qr * cs - qi * sn;
    g_Qi[i] = qr * sn + qi * cs;
    g_Kr[i] = kr * cs - ki * sn;
    g_Ki[i] = kr * sn + ki * cs;
    g_Vr[i] = vr;
    g_Vi[i] = vi;
}

// ---------------- kernel 4: fused complex attention (flash-style) ----------------
// One CTA per (b*h, 64-query tile). 256 threads (ty 0..15, tx 0..15),
// each thread owns 4 q-rows (ty*4+i) and 4 cols (tx+16*j).
// Online softmax over re-scores; weights p*cos(im), p*sin(im) staged in smem for PV.
__global__ __launch_bounds__(256, 1) void attn_kernel() {
    extern __shared__ float sm[];
    float* Qs_re = sm;                       // [64 d][65]
    float* Qs_im = Qs_re + 64 * 65;
    float* Ks_re = Qs_im + 64 * 65;          // [64 d][65]
    float* Ks_im = Ks_re + 64 * 65;
    float* Vs_re = Ks_im + 64 * 65;          // [64 c][64 d]
    float* Vs_im = Vs_re + 64 * 64;
    float* Ws_c  = Vs_im + 64 * 64;          // [64 q][66]
    float* Ws_s  = Ws_c  + 64 * 66;

    const int t  = threadIdx.x;
    const int ty = t >> 4;
    const int tx = t & 15;
    const int q0 = blockIdx.x * 64;
    const int bh = blockIdx.y;

    const size_t hb = (size_t)bh * SEQ * D_HEAD;
    const float* Qr = g_Qr + hb;
    const float* Qi = g_Qi + hb;
    const float* Kr = g_Kr + hb;
    const float* Ki = g_Ki + hb;
    const float* Vr = g_Vr + hb;
    const float* Vi = g_Vi + hb;

    // fill Q tile (transposed [d][q], pitch 65)
#pragma unroll
    for (int ii = 0; ii < 4; ii++) {
        int lin = t + 256 * ii;
        int r  = lin >> 4;       // query row 0..63
        int f4 = lin & 15;       // d float4 index
        float4 a = *(const float4*)(Qr + (q0 + r) * D_HEAD + f4 * 4);
        float4 bq = *(const float4*)(Qi + (q0 + r) * D_HEAD + f4 * 4);
        int db = f4 * 4;
        Qs_re[(db + 0) * 65 + r] = a.x;
        Qs_re[(db + 1) * 65 + r] = a.y;
        Qs_re[(db + 2) * 65 + r] = a.z;
        Qs_re[(db + 3) * 65 + r] = a.w;
        Qs_im[(db + 0) * 65 + r] = bq.x;
        Qs_im[(db + 1) * 65 + r] = bq.y;
        Qs_im[(db + 2) * 65 + r] = bq.z;
        Qs_im[(db + 3) * 65 + r] = bq.w;
    }

    float mrow[4], lrow[4];
    float acc_r[16], acc_i[16];
#pragma unroll
    for (int i = 0; i < 4; i++) { mrow[i] = -1e30f; lrow[i] = 0.0f; }
#pragma unroll
    for (int q = 0; q < 16; q++) { acc_r[q] = 0.0f; acc_i[q] = 0.0f; }

    const float scale = 0.125f;   // 1/sqrt(64)

    for (int kc = 0; kc < SEQ / 64; kc++) {
        int c0 = kc * 64;
        __syncthreads();   // previous PV / Q fill consumed before K/V overwrite

        // fill K (transposed [d][c] pitch 65) and V (natural [c][d] pitch 64)
#pragma unroll
        for (int ii = 0; ii < 4; ii++) {
            int lin = t + 256 * ii;
            int r  = lin >> 4;
            int f4 = lin & 15;
            const int go = (c0 + r) * D_HEAD + f4 * 4;
            float4 kr4 = *(const float4*)(Kr + go);
            float4 ki4 = *(const float4*)(Ki + go);
            int db = f4 * 4;
            Ks_re[(db + 0) * 65 + r] = kr4.x;
            Ks_re[(db + 1) * 65 + r] = kr4.y;
            Ks_re[(db + 2) * 65 + r] = kr4.z;
            Ks_re[(db + 3) * 65 + r] = kr4.w;
            Ks_im[(db + 0) * 65 + r] = ki4.x;
            Ks_im[(db + 1) * 65 + r] = ki4.y;
            Ks_im[(db + 2) * 65 + r] = ki4.z;
            Ks_im[(db + 3) * 65 + r] = ki4.w;
            *(float4*)(Vs_re + r * 64 + f4 * 4) = *(const float4*)(Vr + go);
            *(float4*)(Vs_im + r * 64 + f4 * 4) = *(const float4*)(Vi + go);
        }
        __syncthreads();

        // scores: re = QrKr + QiKi, im = QiKr - QrKi
        float sre[16], simg[16];
#pragma unroll
        for (int q = 0; q < 16; q++) { sre[q] = 0.0f; simg[q] = 0.0f; }

#pragma unroll 8
        for (int d = 0; d < 64; d++) {
            float a_r[4], a_i[4], b_r[4], b_i[4];
#pragma unroll
            for (int i = 0; i < 4; i++) {
                a_r[i] = Qs_re[d * 65 + ty * 4 + i];
                a_i[i] = Qs_im[d * 65 + ty * 4 + i];
            }
#pragma unroll
            for (int j = 0; j < 4; j++) {
                b_r[j] = Ks_re[d * 65 + tx + 16 * j];
                b_i[j] = Ks_im[d * 65 + tx + 16 * j];
            }
#pragma unroll
            for (int i = 0; i < 4; i++)
#pragma unroll
                for (int j = 0; j < 4; j++) {
                    sre[i * 4 + j]  += a_r[i] * b_r[j] + a_i[i] * b_i[j];
                    simg[i * 4 + j] += a_i[i] * b_r[j] - a_r[i] * b_i[j];
                }
        }

        // online softmax (per q-row i; 16 tx lanes share a row -> shfl reduce)
#pragma unroll
        for (int i = 0; i < 4; i++) {
            float cmax = -1e30f;
#pragma unroll
            for (int j = 0; j < 4; j++) {
                sre[i * 4 + j]  *= scale;
                simg[i * 4 + j] *= scale;
                cmax = fmaxf(cmax, sre[i * 4 + j]);
            }
#pragma unroll
            for (int w = 1; w < 16; w <<= 1)
                cmax = fmaxf(cmax, __shfl_xor_sync(0xffffffffu, cmax, w));

            float nm = fmaxf(mrow[i], cmax);
            float alpha = __expf(mrow[i] - nm);
            mrow[i] = nm;

            float rs = 0.0f;
#pragma unroll
            for (int j = 0; j < 4; j++) {
                float pp = __expf(sre[i * 4 + j] - nm);
                sre[i * 4 + j] = pp;
                rs += pp;
            }
#pragma unroll
            for (int w = 1; w < 16; w <<= 1)
                rs += __shfl_xor_sync(0xffffffffu, rs, w);
            lrow[i] = lrow[i] * alpha + rs;

#pragma unroll
            for (int j = 0; j < 4; j++) {
                acc_r[i * 4 + j] *= alpha;
                acc_i[i * 4 + j] *= alpha;
            }
            // w = p*cos(im), p*sin(im) -> smem [q][c] pitch 66
#pragma unroll
            for (int j = 0; j < 4; j++) {
                float sn, cs;
                __sincosf(simg[i * 4 + j], &sn, &cs);
                int qrow = ty * 4 + i;
                int ccol = tx + 16 * j;
                Ws_c[qrow * 66 + ccol] = sre[i * 4 + j] * cs;
                Ws_s[qrow * 66 + ccol] = sre[i * 4 + j] * sn;
            }
        }
        __syncthreads();

        // PV: acc_r += wc*Vr - ws*Vi ; acc_i += wc*Vi + ws*Vr
#pragma unroll 8
        for (int c = 0; c < 64; c++) {
            float wc[4], ws[4], vre[4], vim[4];
#pragma unroll
            for (int i = 0; i < 4; i++) {
                wc[i] = Ws_c[(ty * 4 + i) * 66 + c];
                ws[i] = Ws_s[(ty * 4 + i) * 66 + c];
            }
#pragma unroll
            for (int j = 0; j < 4; j++) {
                vre[j] = Vs_re[c * 64 + tx + 16 * j];
                vim[j] = Vs_im[c * 64 + tx + 16 * j];
            }
#pragma unroll
            for (int i = 0; i < 4; i++)
#pragma unroll
                for (int j = 0; j < 4; j++) {
                    acc_r[i * 4 + j] += wc[i] * vre[j] - ws[i] * vim[j];
                    acc_i[i * 4 + j] += wc[i] * vim[j] + ws[i] * vre[j];
                }
        }
    }

    // epilogue: normalize and merge heads into [B,S,D]
    int b = bh >> 4;
    int h = bh & 15;
#pragma unroll
    for (int i = 0; i < 4; i++) {
        float inv = 1.0f / lrow[i];
        size_t row = (size_t)(b * SEQ + q0 + ty * 4 + i) * D_MODEL;
#pragma unroll
        for (int j = 0; j < 4; j++) {
            int col = h * D_HEAD + tx + 16 * j;
            g_att_r[row + col] = acc_r[i * 4 + j] * inv;
            g_att_i[row + col] = acc_i[i * 4 + j] * inv;
        }
    }
}

// ---------------- launch ----------------
extern "C" void kernel_launch(void* const* d_in, const int* in_sizes, int n_in,
                              void* d_out, int out_size) {
    (void)in_sizes; (void)n_in; (void)out_size;
    const float* x_re    = (const float*)d_in[0];
    const float* x_im    = (const float*)d_in[1];
    const float* wqkv_re = (const float*)d_in[2];
    const float* wqkv_im = (const float*)d_in[3];
    const float* wo_re   = (const float*)d_in[4];
    const float* wo_im   = (const float*)d_in[5];
    float* out = (float*)d_out;

    // resolve device-global scratch addresses
    float *p_qkv_r, *p_qkv_i, *p_att_r, *p_att_i;
    cudaGetSymbolAddress((void**)&p_qkv_r, g_qkv_r);
    cudaGetSymbolAddress((void**)&p_qkv_i, g_qkv_i);
    cudaGetSymbolAddress((void**)&p_att_r, g_att_r);
    cudaGetSymbolAddress((void**)&p_att_i, g_att_i);

    // 1. rope table
    rope_table_kernel<<<(SEQ * D_HEAD + 255) / 256, 256>>>();

    // 2. QKV projection: [2048,1024] x [3072,1024]^T (complex)
    {
        dim3 grid(QKV_N / 64, M_TOK / 64);
        cgemm_kernel<<<grid, 256>>>(x_re, x_im, wqkv_re, wqkv_im,
                                    p_qkv_r, p_qkv_i, M_TOK, QKV_N, D_MODEL);
    }

    // 3. rope apply + head split
    rope_apply_kernel<<<(BHN * SEQ * D_HEAD + 255) / 256, 256>>>();

    // 4. fused attention
    {
        size_t smem = (size_t)(4 * 64 * 65 + 2 * 64 * 64 + 2 * 64 * 66) * sizeof(float);
        cudaFuncSetAttribute(attn_kernel, cudaFuncAttributeMaxDynamicSharedMemorySize, (int)smem);
        dim3 grid(SEQ / 64, BHN);
        attn_kernel<<<grid, 256, smem>>>();
    }

    // 5. output projection -> d_out ([0]=real plane, [1]=imag plane)
    {
        dim3 grid(D_MODEL / 64, M_TOK / 64);
        cgemm_kernel<<<grid, 256>>>(p_att_r, p_att_i, wo_re, wo_im,
                                    out, out + (size_t)M_TOK * D_MODEL,
                                    M_TOK, D_MODEL, D_MODEL);
    }
}

// round 5
// speedup vs baseline: 2.0838x; 2.0838x over previous
#include <cuda_runtime.h>
#include <cuda_bf16.h>
#include <math.h>
#include <stdint.h>

// Problem constants
#define D_MODEL 1024
#define N_HEADS 16
#define D_HEAD  64
#define BATCH   4
#define SEQ     512
#define M_TOK   (BATCH * SEQ)       // 2048
#define QKV_N   (3 * D_MODEL)       // 3072
#define BHN     (BATCH * N_HEADS)   // 64

// ---------------- device scratch (no runtime allocation allowed) ----------------
__device__ float g_rope_cos[SEQ * D_HEAD];
__device__ float g_rope_sin[SEQ * D_HEAD];
__device__ float g_qkv_r[(size_t)M_TOK * QKV_N];
__device__ float g_qkv_i[(size_t)M_TOK * QKV_N];
__device__ float g_Qr[(size_t)BHN * SEQ * D_HEAD];
__device__ float g_Qi[(size_t)BHN * SEQ * D_HEAD];
__device__ float g_Kr[(size_t)BHN * SEQ * D_HEAD];
__device__ float g_Ki[(size_t)BHN * SEQ * D_HEAD];
__device__ float g_Vr[(size_t)BHN * SEQ * D_HEAD];
__device__ float g_Vi[(size_t)BHN * SEQ * D_HEAD];
__device__ float g_att_r[(size_t)M_TOK * D_MODEL];
__device__ float g_att_i[(size_t)M_TOK * D_MODEL];

// bf16 hi/lo splits for tensor-core GEMMs
#define XN   (M_TOK * D_MODEL)      // 2097152
#define WQN  (QKV_N * D_MODEL)      // 3145728
#define WON  (D_MODEL * D_MODEL)    // 1048576
__device__ __nv_bfloat16 g_xrH[XN],  g_xrL[XN],  g_xiH[XN],  g_xiL[XN];
__device__ __nv_bfloat16 g_wqrH[WQN], g_wqrL[WQN], g_wqiH[WQN], g_wqiL[WQN];
__device__ __nv_bfloat16 g_worH[WON], g_worL[WON], g_woiH[WON], g_woiL[WON];
__device__ __nv_bfloat16 g_arH[XN],  g_arL[XN],  g_aiH[XN],  g_aiL[XN];

// ================= PTX helpers (baseline ISA only — no tcgen05) =================
__device__ __forceinline__ uint32_t smem_u32(const void* p) {
    uint32_t a;
    asm("{ .reg .u64 t; cvta.to.shared.u64 t, %1; cvt.u32.u64 %0, t; }" : "=r"(a) : "l"(p));
    return a;
}
__device__ __forceinline__ void cp_async16(uint32_t dst, const void* src) {
    asm volatile("cp.async.cg.shared.global [%0], [%1], 16;" :: "r"(dst), "l"(src));
}
__device__ __forceinline__ void cp_commit() {
    asm volatile("cp.async.commit_group;" ::: "memory");
}
template <int N> __device__ __forceinline__ void cp_wait() {
    asm volatile("cp.async.wait_group %0;" :: "n"(N) : "memory");
}
__device__ __forceinline__ void ldsm_x4(uint32_t* r, uint32_t a) {
    asm volatile("ldmatrix.sync.aligned.m8n8.x4.shared.b16 {%0,%1,%2,%3}, [%4];"
                 : "=r"(r[0]), "=r"(r[1]), "=r"(r[2]), "=r"(r[3]) : "r"(a));
}
__device__ __forceinline__ void ldsm_x2(uint32_t* r, uint32_t a) {
    asm volatile("ldmatrix.sync.aligned.m8n8.x2.shared.b16 {%0,%1}, [%2];"
                 : "=r"(r[0]), "=r"(r[1]) : "r"(a));
}
// D += A(16x16 bf16, row) * B(16x8 bf16, col), fp32 accumulate
__device__ __forceinline__ void mma_bf16(float* c, const uint32_t* a, const uint32_t* b) {
    asm volatile(
        "mma.sync.aligned.m16n8k16.row.col.f32.bf16.bf16.f32 "
        "{%0,%1,%2,%3}, {%4,%5,%6,%7}, {%8,%9}, {%0,%1,%2,%3};"
        : "+f"(c[0]), "+f"(c[1]), "+f"(c[2]), "+f"(c[3])
        : "r"(a[0]), "r"(a[1]), "r"(a[2]), "r"(a[3]), "r"(b[0]), "r"(b[1]));
}

// ---------------- kernel 1: RoPE rotor table ----------------
__global__ void rope_table_kernel() {
    int i = blockIdx.x * blockDim.x + threadIdx.x;
    if (i >= SEQ * D_HEAD) return;
    int s = i / D_HEAD;
    int d = i % D_HEAD;
    float inv_freq = powf(10000.0f, -(float)d / (float)D_HEAD);
    float ang = (float)s * inv_freq;
    float sn, cs;
    sincosf(ang, &sn, &cs);
    g_rope_cos[i] = cs;
    g_rope_sin[i] = sn;
}

// ---------------- kernel 1b: bf16 hi/lo split ----------------
__global__ void split_kernel(const float* __restrict__ src,
                             __nv_bfloat16* __restrict__ hi,
                             __nv_bfloat16* __restrict__ lo, int n4) {
    int i = blockIdx.x * blockDim.x + threadIdx.x;
    if (i >= n4) return;
    float4 v = ((const float4*)src)[i];
    __nv_bfloat16 h0 = __float2bfloat16_rn(v.x);
    __nv_bfloat16 h1 = __float2bfloat16_rn(v.y);
    __nv_bfloat16 h2 = __float2bfloat16_rn(v.z);
    __nv_bfloat16 h3 = __float2bfloat16_rn(v.w);
    __nv_bfloat162 H0 = {h0, h1}, H1 = {h2, h3};
    __nv_bfloat162 L0 = {__float2bfloat16_rn(v.x - __bfloat162float(h0)),
                         __float2bfloat16_rn(v.y - __bfloat162float(h1))};
    __nv_bfloat162 L1 = {__float2bfloat16_rn(v.z - __bfloat162float(h2)),
                         __float2bfloat16_rn(v.w - __bfloat162float(h3))};
    ((__nv_bfloat162*)hi)[i * 2 + 0] = H0;
    ((__nv_bfloat162*)hi)[i * 2 + 1] = H1;
    ((__nv_bfloat162*)lo)[i * 2 + 0] = L0;
    ((__nv_bfloat162*)lo)[i * 2 + 1] = L1;
}

// ---------------- kernel 2: mma.sync complex GEMM  C = A @ B^T ----------------
// A: [M,K] row-major split (ArH,ArL,AiH,AiL), B: [N,K] row-major split.
// CTA tile M=128 x N=64, K-stage 32, double-buffered cp.async.
// 8 warps (4m x 2n), warp tile 32x32, m16n8k16 bf16 HMMA.
// Two fp32 accumulators per element: Cre = Ar*Br - Ai*Bi (via negated-Bi frags),
// Cim = Ar*Bi + Ai*Br. bf16 split: hi*hi + hi*lo + lo*hi (3 MMAs per product).
#define GBM 128
#define GBN 64
#define GBK 32
#define GPITCHB 80                    // bytes per smem row (32 bf16 + 8 pad)
#define A_COMP_B (GBM * GPITCHB)      // 10240
#define B_COMP_B (GBN * GPITCHB)      // 5120
#define STAGE_B  (4 * A_COMP_B + 4 * B_COMP_B)   // 61440
#define G_SMEM   (2 * STAGE_B)        // 122880

__global__ __launch_bounds__(256, 1) void cgemm_tc_kernel(
    const __nv_bfloat16* __restrict__ ArH, const __nv_bfloat16* __restrict__ ArL,
    const __nv_bfloat16* __restrict__ AiH, const __nv_bfloat16* __restrict__ AiL,
    const __nv_bfloat16* __restrict__ BrH, const __nv_bfloat16* __restrict__ BrL,
    const __nv_bfloat16* __restrict__ BiH, const __nv_bfloat16* __restrict__ BiL,
    float* __restrict__ Cre, float* __restrict__ Cim,
    int N, int K)
{
    extern __shared__ __align__(128) char smem[];
    const uint32_t sb = smem_u32(smem);
    const int tid = threadIdx.x;
    const int lane = tid & 31;
    const int wid = tid >> 5;
    const int wm = wid & 3;           // 0..3 -> 32-row strip
    const int wn = wid >> 2;          // 0..1 -> 32-col strip
    const int m0 = blockIdx.y * GBM;
    const int n0 = blockIdx.x * GBN;

    const __nv_bfloat16* Ap[4] = {ArH, ArL, AiH, AiL};
    const __nv_bfloat16* Bp[4] = {BrH, BrL, BiH, BiL};

    auto load_stage = [&](int st, int k0) {
        uint32_t base = sb + st * STAGE_B;
#pragma unroll
        for (int i = 0; i < 8; i++) {                 // A: 2048 16B chunks
            int idx = tid + i * 256;
            int comp = idx >> 9;
            int rem = idx & 511;
            int row = rem >> 2;
            int ch = rem & 3;
            cp_async16(base + comp * A_COMP_B + row * GPITCHB + ch * 16,
                       Ap[comp] + (size_t)(m0 + row) * K + k0 + ch * 8);
        }
        uint32_t bbase = base + 4 * A_COMP_B;
#pragma unroll
        for (int i = 0; i < 4; i++) {                 // B: 1024 16B chunks
            int idx = tid + i * 256;
            int comp = idx >> 8;
            int rem = idx & 255;
            int row = rem >> 2;
            int ch = rem & 3;
            cp_async16(bbase + comp * B_COMP_B + row * GPITCHB + ch * 16,
                       Bp[comp] + (size_t)(n0 + row) * K + k0 + ch * 8);
        }
        cp_commit();
    };

    float cre[2][4][4];
    float cim[2][4][4];
#pragma unroll
    for (int mt = 0; mt < 2; mt++)
#pragma unroll
        for (int nt = 0; nt < 4; nt++)
#pragma unroll
            for (int q = 0; q < 4; q++) { cre[mt][nt][q] = 0.f; cim[mt][nt][q] = 0.f; }

    const int NC = K / GBK;
    load_stage(0, 0);

    for (int c = 0; c < NC; c++) {
        if (c + 1 < NC) { load_stage((c + 1) & 1, (c + 1) * GBK); cp_wait<1>(); }
        else            { cp_wait<0>(); }
        __syncthreads();

        const uint32_t abase = sb + (c & 1) * STAGE_B;
        const uint32_t bbase = abase + 4 * A_COMP_B;

#pragma unroll
        for (int ks = 0; ks < 2; ks++) {              // two k16 steps per stage
            uint32_t af[4][2][4];                     // [comp][mtile][frag]
            uint32_t bfr[4][4][2];                    // [comp][ntile][frag]
#pragma unroll
            for (int comp = 0; comp < 4; comp++)
#pragma unroll
                for (int mt = 0; mt < 2; mt++) {
                    uint32_t addr = abase + comp * A_COMP_B
                        + (uint32_t)(wm * 32 + mt * 16 + (lane & 15)) * GPITCHB
                        + ks * 32 + (lane >> 4) * 16;
                    ldsm_x4(af[comp][mt], addr);
                }
#pragma unroll
            for (int comp = 0; comp < 4; comp++)
#pragma unroll
                for (int nt = 0; nt < 4; nt++) {
                    int c16 = lane & 15;
                    uint32_t addr = bbase + comp * B_COMP_B
                        + (uint32_t)(wn * 32 + nt * 8 + (c16 & 7)) * GPITCHB
                        + ks * 32 + (c16 >> 3) * 16;
                    ldsm_x2(bfr[comp][nt], addr);
                }
            // negated Bi fragments (for Cre subtraction folded into HMMA)
            uint32_t nbi[2][4][2];
#pragma unroll
            for (int h = 0; h < 2; h++)
#pragma unroll
                for (int nt = 0; nt < 4; nt++) {
                    nbi[h][nt][0] = bfr[2 + h][nt][0] ^ 0x80008000u;
                    nbi[h][nt][1] = bfr[2 + h][nt][1] ^ 0x80008000u;
                }
#pragma unroll
            for (int mt = 0; mt < 2; mt++)
#pragma unroll
                for (int nt = 0; nt < 4; nt++) {
                    float* cr = cre[mt][nt];
                    float* ci = cim[mt][nt];
                    // Cre += ArH*BrH + ArH*BrL + ArL*BrH - AiH*BiH - AiH*BiL - AiL*BiH
                    mma_bf16(cr, af[0][mt], bfr[0][nt]);
                    mma_bf16(cr, af[0][mt], bfr[1][nt]);
                    mma_bf16(cr, af[1][mt], bfr[0][nt]);
                    mma_bf16(cr, af[2][mt], nbi[0][nt]);
                    mma_bf16(cr, af[2][mt], nbi[1][nt]);
                    mma_bf16(cr, af[3][mt], nbi[0][nt]);
                    // Cim += ArH*BiH + ArH*BiL + ArL*BiH + AiH*BrH + AiH*BrL + AiL*BrH
                    mma_bf16(ci, af[0][mt], bfr[2][nt]);
                    mma_bf16(ci, af[0][mt], bfr[3][nt]);
                    mma_bf16(ci, af[1][mt], bfr[2][nt]);
                    mma_bf16(ci, af[2][mt], bfr[0][nt]);
                    mma_bf16(ci, af[2][mt], bfr[1][nt]);
                    mma_bf16(ci, af[3][mt], bfr[0][nt]);
                }
        }
        __syncthreads();
    }

    // ---- epilogue: fragment layout c0,c1 -> (row, col..col+1); c2,c3 -> row+8 ----
#pragma unroll
    for (int mt = 0; mt < 2; mt++) {
        int row0 = m0 + wm * 32 + mt * 16 + (lane >> 2);
#pragma unroll
        for (int nt = 0; nt < 4; nt++) {
            int col = n0 + wn * 32 + nt * 8 + (lane & 3) * 2;
            float2 v0 = {cre[mt][nt][0], cre[mt][nt][1]};
            float2 v1 = {cre[mt][nt][2], cre[mt][nt][3]};
            *(float2*)(Cre + (size_t)row0 * N + col) = v0;
            *(float2*)(Cre + (size_t)(row0 + 8) * N + col) = v1;
            float2 w0 = {cim[mt][nt][0], cim[mt][nt][1]};
            float2 w1 = {cim[mt][nt][2], cim[mt][nt][3]};
            *(float2*)(Cim + (size_t)row0 * N + col) = w0;
            *(float2*)(Cim + (size_t)(row0 + 8) * N + col) = w1;
        }
    }
}

// ---------------- kernel 3: RoPE apply + split heads ----------------
__global__ void rope_apply_kernel() {
    int i = blockIdx.x * blockDim.x + threadIdx.x;
    if (i >= BHN * SEQ * D_HEAD) return;
    int d = i & 63;
    int s = (i >> 6) & 511;
    int h = (i >> 15) & 15;
    int b = i >> 19;

    size_t base = (size_t)(b * SEQ + s) * QKV_N + h * D_HEAD + d;
    float qr = g_qkv_r[base];
    float qi = g_qkv_i[base];
    float kr = g_qkv_r[base + D_MODEL];
    float ki = g_qkv_i[base + D_MODEL];
    float vr = g_qkv_r[base + 2 * D_MODEL];
    float vi = g_qkv_i[base + 2 * D_MODEL];

    float cs = g_rope_cos[s * D_HEAD + d];
    float sn = g_rope_sin[s * D_HEAD + d];

    g_Qr[i] = qr * cs - qi * sn;
    g_Qi[i] = qr * sn + qi * cs;
    g_Kr[i] = kr * cs - ki * sn;
    g_Ki[i] = kr * sn + ki * cs;
    g_Vr[i] = vr;
    g_Vi[i] = vi;
}

// ---------------- kernel 4: fused complex attention (flash-style, fp32) ----------------
__global__ __launch_bounds__(256, 1) void attn_kernel() {
    extern __shared__ float sm[];
    float* Qs_re = sm;                       // [64 d][65]
    float* Qs_im = Qs_re + 64 * 65;
    float* Ks_re = Qs_im + 64 * 65;          // [64 d][65]
    float* Ks_im = Ks_re + 64 * 65;
    float* Vs_re = Ks_im + 64 * 65;          // [64 c][64 d]
    float* Vs_im = Vs_re + 64 * 64;
    float* Ws_c  = Vs_im + 64 * 64;          // [64 q][66]
    float* Ws_s  = Ws_c  + 64 * 66;

    const int t  = threadIdx.x;
    const int ty = t >> 4;
    const int tx = t & 15;
    const int q0 = blockIdx.x * 64;
    const int bh = blockIdx.y;

    const size_t hb = (size_t)bh * SEQ * D_HEAD;
    const float* Qr = g_Qr + hb;
    const float* Qi = g_Qi + hb;
    const float* Kr = g_Kr + hb;
    const float* Ki = g_Ki + hb;
    const float* Vr = g_Vr + hb;
    const float* Vi = g_Vi + hb;

#pragma unroll
    for (int ii = 0; ii < 4; ii++) {
        int lin = t + 256 * ii;
        int r  = lin >> 4;
        int f4 = lin & 15;
        float4 a = *(const float4*)(Qr + (q0 + r) * D_HEAD + f4 * 4);
        float4 bq = *(const float4*)(Qi + (q0 + r) * D_HEAD + f4 * 4);
        int db = f4 * 4;
        Qs_re[(db + 0) * 65 + r] = a.x;
        Qs_re[(db + 1) * 65 + r] = a.y;
        Qs_re[(db + 2) * 65 + r] = a.z;
        Qs_re[(db + 3) * 65 + r] = a.w;
        Qs_im[(db + 0) * 65 + r] = bq.x;
        Qs_im[(db + 1) * 65 + r] = bq.y;
        Qs_im[(db + 2) * 65 + r] = bq.z;
        Qs_im[(db + 3) * 65 + r] = bq.w;
    }

    float mrow[4], lrow[4];
    float acc_r[16], acc_i[16];
#pragma unroll
    for (int i = 0; i < 4; i++) { mrow[i] = -1e30f; lrow[i] = 0.0f; }
#pragma unroll
    for (int q = 0; q < 16; q++) { acc_r[q] = 0.0f; acc_i[q] = 0.0f; }

    const float scale = 0.125f;

    for (int kc = 0; kc < SEQ / 64; kc++) {
        int c0 = kc * 64;
        __syncthreads();

#pragma unroll
        for (int ii = 0; ii < 4; ii++) {
            int lin = t + 256 * ii;
            int r  = lin >> 4;
            int f4 = lin & 15;
            const int go = (c0 + r) * D_HEAD + f4 * 4;
            float4 kr4 = *(const float4*)(Kr + go);
            float4 ki4 = *(const float4*)(Ki + go);
            int db = f4 * 4;
            Ks_re[(db + 0) * 65 + r] = kr4.x;
            Ks_re[(db + 1) * 65 + r] = kr4.y;
            Ks_re[(db + 2) * 65 + r] = kr4.z;
            Ks_re[(db + 3) * 65 + r] = kr4.w;
            Ks_im[(db + 0) * 65 + r] = ki4.x;
            Ks_im[(db + 1) * 65 + r] = ki4.y;
            Ks_im[(db + 2) * 65 + r] = ki4.z;
            Ks_im[(db + 3) * 65 + r] = ki4.w;
            *(float4*)(Vs_re + r * 64 + f4 * 4) = *(const float4*)(Vr + go);
            *(float4*)(Vs_im + r * 64 + f4 * 4) = *(const float4*)(Vi + go);
        }
        __syncthreads();

        float sre[16], simg[16];
#pragma unroll
        for (int q = 0; q < 16; q++) { sre[q] = 0.0f; simg[q] = 0.0f; }

#pragma unroll 8
        for (int d = 0; d < 64; d++) {
            float a_r[4], a_i[4], b_r[4], b_i[4];
#pragma unroll
            for (int i = 0; i < 4; i++) {
                a_r[i] = Qs_re[d * 65 + ty * 4 + i];
                a_i[i] = Qs_im[d * 65 + ty * 4 + i];
            }
#pragma unroll
            for (int j = 0; j < 4; j++) {
                b_r[j] = Ks_re[d * 65 + tx + 16 * j];
                b_i[j] = Ks_im[d * 65 + tx + 16 * j];
            }
#pragma unroll
            for (int i = 0; i < 4; i++)
#pragma unroll
                for (int j = 0; j < 4; j++) {
                    sre[i * 4 + j]  += a_r[i] * b_r[j] + a_i[i] * b_i[j];
                    simg[i * 4 + j] += a_i[i] * b_r[j] - a_r[i] * b_i[j];
                }
        }

#pragma unroll
        for (int i = 0; i < 4; i++) {
            float cmax = -1e30f;
#pragma unroll
            for (int j = 0; j < 4; j++) {
                sre[i * 4 + j]  *= scale;
                simg[i * 4 + j] *= scale;
                cmax = fmaxf(cmax, sre[i * 4 + j]);
            }
#pragma unroll
            for (int w = 1; w < 16; w <<= 1)
                cmax = fmaxf(cmax, __shfl_xor_sync(0xffffffffu, cmax, w));

            float nm = fmaxf(mrow[i], cmax);
            float alpha = __expf(mrow[i] - nm);
            mrow[i] = nm;

            float rs = 0.0f;
#pragma unroll
            for (int j = 0; j < 4; j++) {
                float pp = __expf(sre[i * 4 + j] - nm);
                sre[i * 4 + j] = pp;
                rs += pp;
            }
#pragma unroll
            for (int w = 1; w < 16; w <<= 1)
                rs += __shfl_xor_sync(0xffffffffu, rs, w);
            lrow[i] = lrow[i] * alpha + rs;

#pragma unroll
            for (int j = 0; j < 4; j++) {
                acc_r[i * 4 + j] *= alpha;
                acc_i[i * 4 + j] *= alpha;
            }
#pragma unroll
            for (int j = 0; j < 4; j++) {
                float sn, cs;
                __sincosf(simg[i * 4 + j], &sn, &cs);
                int qrow = ty * 4 + i;
                int ccol = tx + 16 * j;
                Ws_c[qrow * 66 + ccol] = sre[i * 4 + j] * cs;
                Ws_s[qrow * 66 + ccol] = sre[i * 4 + j] * sn;
            }
        }
        __syncthreads();

#pragma unroll 8
        for (int c = 0; c < 64; c++) {
            float wc[4], ws[4], vre[4], vim[4];
#pragma unroll
            for (int i = 0; i < 4; i++) {
                wc[i] = Ws_c[(ty * 4 + i) * 66 + c];
                ws[i] = Ws_s[(ty * 4 + i) * 66 + c];
            }
#pragma unroll
            for (int j = 0; j < 4; j++) {
                vre[j] = Vs_re[c * 64 + tx + 16 * j];
                vim[j] = Vs_im[c * 64 + tx + 16 * j];
            }
#pragma unroll
            for (int i = 0; i < 4; i++)
#pragma unroll
                for (int j = 0; j < 4; j++) {
                    acc_r[i * 4 + j] += wc[i] * vre[j] - ws[i] * vim[j];
                    acc_i[i * 4 + j] += wc[i] * vim[j] + ws[i] * vre[j];
                }
        }
    }

    int b = bh >> 4;
    int h = bh & 15;
#pragma unroll
    for (int i = 0; i < 4; i++) {
        float inv = 1.0f / lrow[i];
        size_t row = (size_t)(b * SEQ + q0 + ty * 4 + i) * D_MODEL;
#pragma unroll
        for (int j = 0; j < 4; j++) {
            int col = h * D_HEAD + tx + 16 * j;
            g_att_r[row + col] = acc_r[i * 4 + j] * inv;
            g_att_i[row + col] = acc_i[i * 4 + j] * inv;
        }
    }
}

// ---------------- launch ----------------
static inline void launch_split(const float* src, __nv_bfloat16* hi, __nv_bfloat16* lo, int n) {
    int n4 = n / 4;
    split_kernel<<<(n4 + 255) / 256, 256>>>(src, hi, lo, n4);
}

extern "C" void kernel_launch(void* const* d_in, const int* in_sizes, int n_in,
                              void* d_out, int out_size) {
    (void)in_sizes; (void)n_in; (void)out_size;
    const float* x_re    = (const float*)d_in[0];
    const float* x_im    = (const float*)d_in[1];
    const float* wqkv_re = (const float*)d_in[2];
    const float* wqkv_im = (const float*)d_in[3];
    const float* wo_re   = (const float*)d_in[4];
    const float* wo_im   = (const float*)d_in[5];
    float* out = (float*)d_out;

    float *p_qkv_r, *p_qkv_i, *p_att_r, *p_att_i;
    cudaGetSymbolAddress((void**)&p_qkv_r, g_qkv_r);
    cudaGetSymbolAddress((void**)&p_qkv_i, g_qkv_i);
    cudaGetSymbolAddress((void**)&p_att_r, g_att_r);
    cudaGetSymbolAddress((void**)&p_att_i, g_att_i);

    __nv_bfloat16 *xrH, *xrL, *xiH, *xiL, *wqrH, *wqrL, *wqiH, *wqiL;
    __nv_bfloat16 *worH, *worL, *woiH, *woiL, *arH, *arL, *aiH, *aiL;
    cudaGetSymbolAddress((void**)&xrH, g_xrH);   cudaGetSymbolAddress((void**)&xrL, g_xrL);
    cudaGetSymbolAddress((void**)&xiH, g_xiH);   cudaGetSymbolAddress((void**)&xiL, g_xiL);
    cudaGetSymbolAddress((void**)&wqrH, g_wqrH); cudaGetSymbolAddress((void**)&wqrL, g_wqrL);
    cudaGetSymbolAddress((void**)&wqiH, g_wqiH); cudaGetSymbolAddress((void**)&wqiL, g_wqiL);
    cudaGetSymbolAddress((void**)&worH, g_worH); cudaGetSymbolAddress((void**)&worL, g_worL);
    cudaGetSymbolAddress((void**)&woiH, g_woiH); cudaGetSymbolAddress((void**)&woiL, g_woiL);
    cudaGetSymbolAddress((void**)&arH, g_arH);   cudaGetSymbolAddress((void**)&arL, g_arL);
    cudaGetSymbolAddress((void**)&aiH, g_aiH);   cudaGetSymbolAddress((void**)&aiL, g_aiL);

    cudaFuncSetAttribute(cgemm_tc_kernel,
                         cudaFuncAttributeMaxDynamicSharedMemorySize, G_SMEM);
    size_t attn_smem = (size_t)(4 * 64 * 65 + 2 * 64 * 64 + 2 * 64 * 66) * sizeof(float);
    cudaFuncSetAttribute(attn_kernel,
                         cudaFuncAttributeMaxDynamicSharedMemorySize, (int)attn_smem);

    // 1. rope table
    rope_table_kernel<<<(SEQ * D_HEAD + 255) / 256, 256>>>();

    // 2. bf16 splits of inputs + weights
    launch_split(x_re, xrH, xrL, XN);
    launch_split(x_im, xiH, xiL, XN);
    launch_split(wqkv_re, wqrH, wqrL, WQN);
    launch_split(wqkv_im, wqiH, wqiL, WQN);
    launch_split(wo_re, worH, worL, WON);
    launch_split(wo_im, woiH, woiL, WON);

    // 3. QKV projection (tensor cores): [2048 x 3072 x 1024] complex
    {
        dim3 grid(QKV_N / GBN, M_TOK / GBM);
        cgemm_tc_kernel<<<grid, 256, G_SMEM>>>(
            xrH, xrL, xiH, xiL, wqrH, wqrL, wqiH, wqiL,
            p_qkv_r, p_qkv_i, QKV_N, D_MODEL);
    }

    // 4. rope apply + head split
    rope_apply_kernel<<<(BHN * SEQ * D_HEAD + 255) / 256, 256>>>();

    // 5. fused attention (fp32, at its scalar roofline)
    {
        dim3 grid(SEQ / 64, BHN);
        attn_kernel<<<grid, 256, attn_smem>>>();
    }

    // 6. split attention output, output projection (tensor cores) -> d_out
    launch_split(p_att_r, arH, arL, XN);
    launch_split(p_att_i, aiH, aiL, XN);
    {
        dim3 grid(D_MODEL / GBN, M_TOK / GBM);
        cgemm_tc_kernel<<<grid, 256, G_SMEM>>>(
            arH, arL, aiH, aiL, worH, worL, woiH, woiL,
            out, out + (size_t)M_TOK * D_MODEL, D_MODEL, D_MODEL);
    }
}

// round 6
// speedup vs baseline: 2.9284x; 1.4054x over previous
#include <cuda_runtime.h>
#include <cuda_bf16.h>
#include <math.h>
#include <stdint.h>

// Problem constants
#define D_MODEL 1024
#define N_HEADS 16
#define D_HEAD  64
#define BATCH   4
#define SEQ     512
#define M_TOK   (BATCH * SEQ)       // 2048
#define QKV_N   (3 * D_MODEL)       // 3072
#define BHN     (BATCH * N_HEADS)   // 64
#define QS      (BHN * SEQ * D_HEAD) // 2097152

// ---------------- device scratch (no runtime allocation allowed) ----------------
__device__ float g_rope_cos[SEQ * D_HEAD];
__device__ float g_rope_sin[SEQ * D_HEAD];
__device__ float g_qkv_r[(size_t)M_TOK * QKV_N];
__device__ float g_qkv_i[(size_t)M_TOK * QKV_N];
__device__ float g_att_r[(size_t)M_TOK * D_MODEL];
__device__ float g_att_i[(size_t)M_TOK * D_MODEL];

// bf16 hi/lo splits for projection GEMMs
#define XN   (M_TOK * D_MODEL)      // 2097152
#define WQN  (QKV_N * D_MODEL)      // 3145728
#define WON  (D_MODEL * D_MODEL)    // 1048576
__device__ __nv_bfloat16 g_xrH[XN],  g_xrL[XN],  g_xiH[XN],  g_xiL[XN];
__device__ __nv_bfloat16 g_wqrH[WQN], g_wqrL[WQN], g_wqiH[WQN], g_wqiL[WQN];
__device__ __nv_bfloat16 g_worH[WON], g_worL[WON], g_woiH[WON], g_woiL[WON];
__device__ __nv_bfloat16 g_arH[XN],  g_arL[XN],  g_aiH[XN],  g_aiL[XN];

// bf16 hi/lo splits for attention (written by rope_apply)
// Q, K: [bh][s][d] token-major.  V: [bh][d][s] dim-major (transposed, B-frag ready).
__device__ __nv_bfloat16 g_QrH[QS], g_QrL[QS], g_QiH[QS], g_QiL[QS];
__device__ __nv_bfloat16 g_KrH[QS], g_KrL[QS], g_KiH[QS], g_KiL[QS];
__device__ __nv_bfloat16 g_VrH[QS], g_VrL[QS], g_ViH[QS], g_ViL[QS];

// ================= PTX helpers (baseline ISA only — no tcgen05) =================
__device__ __forceinline__ uint32_t smem_u32(const void* p) {
    uint32_t a;
    asm("{ .reg .u64 t; cvta.to.shared.u64 t, %1; cvt.u32.u64 %0, t; }" : "=r"(a) : "l"(p));
    return a;
}
__device__ __forceinline__ void cp_async16(uint32_t dst, const void* src) {
    asm volatile("cp.async.cg.shared.global [%0], [%1], 16;" :: "r"(dst), "l"(src));
}
__device__ __forceinline__ void cp_commit() {
    asm volatile("cp.async.commit_group;" ::: "memory");
}
template <int N> __device__ __forceinline__ void cp_wait() {
    asm volatile("cp.async.wait_group %0;" :: "n"(N) : "memory");
}
__device__ __forceinline__ void ldsm_x4(uint32_t* r, uint32_t a) {
    asm volatile("ldmatrix.sync.aligned.m8n8.x4.shared.b16 {%0,%1,%2,%3}, [%4];"
                 : "=r"(r[0]), "=r"(r[1]), "=r"(r[2]), "=r"(r[3]) : "r"(a));
}
__device__ __forceinline__ void ldsm_x2(uint32_t* r, uint32_t a) {
    asm volatile("ldmatrix.sync.aligned.m8n8.x2.shared.b16 {%0,%1}, [%2];"
                 : "=r"(r[0]), "=r"(r[1]) : "r"(a));
}
// D += A(16x16 bf16, row) * B(16x8 bf16, col), fp32 accumulate
__device__ __forceinline__ void mma_bf16(float* c, const uint32_t* a, const uint32_t* b) {
    asm volatile(
        "mma.sync.aligned.m16n8k16.row.col.f32.bf16.bf16.f32 "
        "{%0,%1,%2,%3}, {%4,%5,%6,%7}, {%8,%9}, {%0,%1,%2,%3};"
        : "+f"(c[0]), "+f"(c[1]), "+f"(c[2]), "+f"(c[3])
        : "r"(a[0]), "r"(a[1]), "r"(a[2]), "r"(a[3]), "r"(b[0]), "r"(b[1]));
}
__device__ __forceinline__ void bsplit(float v, __nv_bfloat16& h, __nv_bfloat16& l) {
    h = __float2bfloat16_rn(v);
    l = __float2bfloat16_rn(v - __bfloat162float(h));
}
__device__ __forceinline__ uint32_t packbf2(__nv_bfloat16 a, __nv_bfloat16 b) {
    __nv_bfloat162 t{a, b};
    return *reinterpret_cast<uint32_t*>(&t);
}
#define SGNX2 0x80008000u

// ---------------- kernel 1: RoPE rotor table ----------------
__global__ void rope_table_kernel() {
    int i = blockIdx.x * blockDim.x + threadIdx.x;
    if (i >= SEQ * D_HEAD) return;
    int s = i / D_HEAD;
    int d = i % D_HEAD;
    float inv_freq = powf(10000.0f, -(float)d / (float)D_HEAD);
    float ang = (float)s * inv_freq;
    float sn, cs;
    sincosf(ang, &sn, &cs);
    g_rope_cos[i] = cs;
    g_rope_sin[i] = sn;
}

// ---------------- kernel 1b: bf16 hi/lo split ----------------
__global__ void split_kernel(const float* __restrict__ src,
                             __nv_bfloat16* __restrict__ hi,
                             __nv_bfloat16* __restrict__ lo, int n4) {
    int i = blockIdx.x * blockDim.x + threadIdx.x;
    if (i >= n4) return;
    float4 v = ((const float4*)src)[i];
    __nv_bfloat16 h0, h1, h2, h3, l0, l1, l2, l3;
    bsplit(v.x, h0, l0); bsplit(v.y, h1, l1);
    bsplit(v.z, h2, l2); bsplit(v.w, h3, l3);
    ((uint32_t*)hi)[i * 2 + 0] = packbf2(h0, h1);
    ((uint32_t*)hi)[i * 2 + 1] = packbf2(h2, h3);
    ((uint32_t*)lo)[i * 2 + 0] = packbf2(l0, l1);
    ((uint32_t*)lo)[i * 2 + 1] = packbf2(l2, l3);
}

// ---------------- kernel 2: mma.sync complex GEMM  C = A @ B^T (unchanged, proven) ----------------
#define GBM 128
#define GBN 64
#define GBK 32
#define GPITCHB 80
#define A_COMP_B (GBM * GPITCHB)
#define B_COMP_B (GBN * GPITCHB)
#define STAGE_B  (4 * A_COMP_B + 4 * B_COMP_B)
#define G_SMEM   (2 * STAGE_B)

__global__ __launch_bounds__(256, 1) void cgemm_tc_kernel(
    const __nv_bfloat16* __restrict__ ArH, const __nv_bfloat16* __restrict__ ArL,
    const __nv_bfloat16* __restrict__ AiH, const __nv_bfloat16* __restrict__ AiL,
    const __nv_bfloat16* __restrict__ BrH, const __nv_bfloat16* __restrict__ BrL,
    const __nv_bfloat16* __restrict__ BiH, const __nv_bfloat16* __restrict__ BiL,
    float* __restrict__ Cre, float* __restrict__ Cim,
    int N, int K)
{
    extern __shared__ __align__(128) char smem[];
    const uint32_t sb = smem_u32(smem);
    const int tid = threadIdx.x;
    const int lane = tid & 31;
    const int wid = tid >> 5;
    const int wm = wid & 3;
    const int wn = wid >> 2;
    const int m0 = blockIdx.y * GBM;
    const int n0 = blockIdx.x * GBN;

    const __nv_bfloat16* Ap[4] = {ArH, ArL, AiH, AiL};
    const __nv_bfloat16* Bp[4] = {BrH, BrL, BiH, BiL};

    auto load_stage = [&](int st, int k0) {
        uint32_t base = sb + st * STAGE_B;
#pragma unroll
        for (int i = 0; i < 8; i++) {
            int idx = tid + i * 256;
            int comp = idx >> 9;
            int rem = idx & 511;
            int row = rem >> 2;
            int ch = rem & 3;
            cp_async16(base + comp * A_COMP_B + row * GPITCHB + ch * 16,
                       Ap[comp] + (size_t)(m0 + row) * K + k0 + ch * 8);
        }
        uint32_t bbase = base + 4 * A_COMP_B;
#pragma unroll
        for (int i = 0; i < 4; i++) {
            int idx = tid + i * 256;
            int comp = idx >> 8;
            int rem = idx & 255;
            int row = rem >> 2;
            int ch = rem & 3;
            cp_async16(bbase + comp * B_COMP_B + row * GPITCHB + ch * 16,
                       Bp[comp] + (size_t)(n0 + row) * K + k0 + ch * 8);
        }
        cp_commit();
    };

    float cre[2][4][4];
    float cim[2][4][4];
#pragma unroll
    for (int mt = 0; mt < 2; mt++)
#pragma unroll
        for (int nt = 0; nt < 4; nt++)
#pragma unroll
            for (int q = 0; q < 4; q++) { cre[mt][nt][q] = 0.f; cim[mt][nt][q] = 0.f; }

    const int NC = K / GBK;
    load_stage(0, 0);

    for (int c = 0; c < NC; c++) {
        if (c + 1 < NC) { load_stage((c + 1) & 1, (c + 1) * GBK); cp_wait<1>(); }
        else            { cp_wait<0>(); }
        __syncthreads();

        const uint32_t abase = sb + (c & 1) * STAGE_B;
        const uint32_t bbase = abase + 4 * A_COMP_B;

#pragma unroll
        for (int ks = 0; ks < 2; ks++) {
            uint32_t af[4][2][4];
            uint32_t bfr[4][4][2];
#pragma unroll
            for (int comp = 0; comp < 4; comp++)
#pragma unroll
                for (int mt = 0; mt < 2; mt++) {
                    uint32_t addr = abase + comp * A_COMP_B
                        + (uint32_t)(wm * 32 + mt * 16 + (lane & 15)) * GPITCHB
                        + ks * 32 + (lane >> 4) * 16;
                    ldsm_x4(af[comp][mt], addr);
                }
#pragma unroll
            for (int comp = 0; comp < 4; comp++)
#pragma unroll
                for (int nt = 0; nt < 4; nt++) {
                    int c16 = lane & 15;
                    uint32_t addr = bbase + comp * B_COMP_B
                        + (uint32_t)(wn * 32 + nt * 8 + (c16 & 7)) * GPITCHB
                        + ks * 32 + (c16 >> 3) * 16;
                    ldsm_x2(bfr[comp][nt], addr);
                }
            uint32_t nbi[2][4][2];
#pragma unroll
            for (int h = 0; h < 2; h++)
#pragma unroll
                for (int nt = 0; nt < 4; nt++) {
                    nbi[h][nt][0] = bfr[2 + h][nt][0] ^ SGNX2;
                    nbi[h][nt][1] = bfr[2 + h][nt][1] ^ SGNX2;
                }
#pragma unroll
            for (int mt = 0; mt < 2; mt++)
#pragma unroll
                for (int nt = 0; nt < 4; nt++) {
                    float* cr = cre[mt][nt];
                    float* ci = cim[mt][nt];
                    mma_bf16(cr, af[0][mt], bfr[0][nt]);
                    mma_bf16(cr, af[0][mt], bfr[1][nt]);
                    mma_bf16(cr, af[1][mt], bfr[0][nt]);
                    mma_bf16(cr, af[2][mt], nbi[0][nt]);
                    mma_bf16(cr, af[2][mt], nbi[1][nt]);
                    mma_bf16(cr, af[3][mt], nbi[0][nt]);
                    mma_bf16(ci, af[0][mt], bfr[2][nt]);
                    mma_bf16(ci, af[0][mt], bfr[3][nt]);
                    mma_bf16(ci, af[1][mt], bfr[2][nt]);
                    mma_bf16(ci, af[2][mt], bfr[0][nt]);
                    mma_bf16(ci, af[2][mt], bfr[1][nt]);
                    mma_bf16(ci, af[3][mt], bfr[0][nt]);
                }
        }
        __syncthreads();
    }

#pragma unroll
    for (int mt = 0; mt < 2; mt++) {
        int row0 = m0 + wm * 32 + mt * 16 + (lane >> 2);
#pragma unroll
        for (int nt = 0; nt < 4; nt++) {
            int col = n0 + wn * 32 + nt * 8 + (lane & 3) * 2;
            float2 v0 = {cre[mt][nt][0], cre[mt][nt][1]};
            float2 v1 = {cre[mt][nt][2], cre[mt][nt][3]};
            *(float2*)(Cre + (size_t)row0 * N + col) = v0;
            *(float2*)(Cre + (size_t)(row0 + 8) * N + col) = v1;
            float2 w0 = {cim[mt][nt][0], cim[mt][nt][1]};
            float2 w1 = {cim[mt][nt][2], cim[mt][nt][3]};
            *(float2*)(Cim + (size_t)row0 * N + col) = w0;
            *(float2*)(Cim + (size_t)(row0 + 8) * N + col) = w1;
        }
    }
}

// ---------------- kernel 3: RoPE apply + head split + bf16 hi/lo emit ----------------
__global__ void rope_apply_kernel() {
    int i = blockIdx.x * blockDim.x + threadIdx.x;
    if (i >= QS) return;
    int d = i & 63;
    int s = (i >> 6) & 511;
    int bh = i >> 15;
    int h = bh & 15;
    int b = bh >> 4;

    size_t base = (size_t)(b * SEQ + s) * QKV_N + h * D_HEAD + d;
    float qr = g_qkv_r[base];
    float qi = g_qkv_i[base];
    float kr = g_qkv_r[base + D_MODEL];
    float ki = g_qkv_i[base + D_MODEL];
    float vr = g_qkv_r[base + 2 * D_MODEL];
    float vi = g_qkv_i[base + 2 * D_MODEL];

    float cs = g_rope_cos[s * D_HEAD + d];
    float sn = g_rope_sin[s * D_HEAD + d];

    float Qr = qr * cs - qi * sn;
    float Qi = qr * sn + qi * cs;
    float Kr = kr * cs - ki * sn;
    float Ki = kr * sn + ki * cs;

    __nv_bfloat16 H, L;
    bsplit(Qr, H, L); g_QrH[i] = H; g_QrL[i] = L;
    bsplit(Qi, H, L); g_QiH[i] = H; g_QiL[i] = L;
    bsplit(Kr, H, L); g_KrH[i] = H; g_KrL[i] = L;
    bsplit(Ki, H, L); g_KiH[i] = H; g_KiL[i] = L;

    size_t j = (size_t)bh * (64 * SEQ) + (size_t)d * SEQ + s;   // transposed [bh][d][s]
    bsplit(vr, H, L); g_VrH[j] = H; g_VrL[j] = L;
    bsplit(vi, H, L); g_ViH[j] = H; g_ViL[j] = L;
}

// ---------------- kernel 4: tensor-core flash attention (complex) ----------------
// CTA: 128 queries x one (b,h). 8 warps, warp w owns rows w*16..w*16+15.
// Per kc (64-key block): scores S_re/S_im via 12 split-HMMA per micro-tile;
// online softmax; W = p*cos/p*sin repacked in registers as A-frags; PV via 12 HMMA.
#define AP    144                    // smem row pitch (64 bf16 = 128B + 16B pad)
#define QCOMP (128 * AP)             // 18432 per Q component
#define KCOMP (64 * AP)              // 9216 per K/Vt component
#define SQ_BYTES (4 * QCOMP)         // 73728
#define ASTAGE   (8 * KCOMP)         // 73728 (KrH,KrL,KiH,KiL,VrH,VrL,ViH,ViL)
#define A_SMEM   (SQ_BYTES + 2 * ASTAGE)  // 221184

__global__ __launch_bounds__(256, 1) void attn_tc_kernel() {
    extern __shared__ __align__(128) char smem[];
    const uint32_t sb = smem_u32(smem);
    const int tid = threadIdx.x;
    const int lane = tid & 31;
    const int w = tid >> 5;
    const int grp = lane >> 2;
    const int tq = lane & 3;
    const int q0 = blockIdx.x * 128;
    const int bh = blockIdx.y;
    const float scale = 0.125f;

    const __nv_bfloat16* gQ[4] = {g_QrH, g_QrL, g_QiH, g_QiL};
    const __nv_bfloat16* gK[4] = {g_KrH, g_KrL, g_KiH, g_KiL};
    const __nv_bfloat16* gV[4] = {g_VrH, g_VrL, g_ViH, g_ViL};
    const size_t hbQ = (size_t)bh * (SEQ * 64);

    // prologue: Q tile (persistent) + stage 0
    {
#pragma unroll
        for (int it = 0; it < 16; it++) {
            int idx = tid + it * 256;
            int comp = idx >> 10;
            int rem = idx & 1023;
            int row = rem >> 3;
            int ch = rem & 7;
            cp_async16(sb + comp * QCOMP + row * AP + ch * 16,
                       gQ[comp] + hbQ + (size_t)(q0 + row) * 64 + ch * 8);
        }
    }
    auto load_stage = [&](int st, int c0) {
        uint32_t base = sb + SQ_BYTES + st * ASTAGE;
#pragma unroll
        for (int it = 0; it < 16; it++) {
            int idx = tid + it * 256;
            int comp = idx >> 9;           // 0..7
            int rem = idx & 511;
            int row = rem >> 3;
            int ch = rem & 7;
            const __nv_bfloat16* src;
            if (comp < 4) src = gK[comp] + hbQ + (size_t)(c0 + row) * 64 + ch * 8;
            else          src = gV[comp - 4] + hbQ + (size_t)row * SEQ + c0 + ch * 8;
            cp_async16(base + comp * KCOMP + row * AP + ch * 16, src);
        }
        cp_commit();
    };
    load_stage(0, 0);

    float or_[8][4], oi_[8][4];
#pragma unroll
    for (int nt = 0; nt < 8; nt++)
#pragma unroll
        for (int q = 0; q < 4; q++) { or_[nt][q] = 0.f; oi_[nt][q] = 0.f; }
    float m0 = -1e30f, m1 = -1e30f, l0 = 0.f, l1 = 0.f;

    for (int kc = 0; kc < 8; kc++) {
        if (kc < 7) { load_stage((kc + 1) & 1, (kc + 1) * 64); cp_wait<1>(); }
        else        { cp_wait<0>(); }
        __syncthreads();
        const uint32_t stg = sb + SQ_BYTES + (kc & 1) * ASTAGE;

        // ---- scores ----
        float sre[8][4], sim[8][4];
#pragma unroll
        for (int nt = 0; nt < 8; nt++)
#pragma unroll
            for (int q = 0; q < 4; q++) { sre[nt][q] = 0.f; sim[nt][q] = 0.f; }

        const uint32_t krow = ((lane >> 4) & 1) * 8 + (lane & 7);
        const uint32_t koff = ((lane >> 3) & 1) * 16;

#pragma unroll
        for (int ks = 0; ks < 4; ks++) {
            uint32_t qa = sb + (uint32_t)(w * 16 + (lane & 15)) * AP + ks * 32 + (lane >> 4) * 16;
            uint32_t qrH[4], qrL[4], qiH[4], qiL[4];
            ldsm_x4(qrH, qa + 0 * QCOMP);
            ldsm_x4(qrL, qa + 1 * QCOMP);
            ldsm_x4(qiH, qa + 2 * QCOMP);
            ldsm_x4(qiL, qa + 3 * QCOMP);
#pragma unroll
            for (int nt16 = 0; nt16 < 4; nt16++) {
                uint32_t kb = stg + (uint32_t)(nt16 * 16 + krow) * AP + ks * 32 + koff;
                uint32_t krH[4], krL[4], kiH[4], kiL[4];
                ldsm_x4(krH, kb + 0 * KCOMP);
                ldsm_x4(krL, kb + 1 * KCOMP);
                ldsm_x4(kiH, kb + 2 * KCOMP);
                ldsm_x4(kiL, kb + 3 * KCOMP);
#pragma unroll
                for (int hf = 0; hf < 2; hf++) {
                    int nt = nt16 * 2 + hf;
                    const uint32_t* bRH = krH + hf * 2;
                    const uint32_t* bRL = krL + hf * 2;
                    const uint32_t* bIH = kiH + hf * 2;
                    const uint32_t* bIL = kiL + hf * 2;
                    uint32_t nIH[2] = {bIH[0] ^ SGNX2, bIH[1] ^ SGNX2};
                    uint32_t nIL[2] = {bIL[0] ^ SGNX2, bIL[1] ^ SGNX2};
                    // re = QrKr + QiKi
                    mma_bf16(sre[nt], qrH, bRH);
                    mma_bf16(sre[nt], qrH, bRL);
                    mma_bf16(sre[nt], qrL, bRH);
                    mma_bf16(sre[nt], qiH, bIH);
                    mma_bf16(sre[nt], qiH, bIL);
                    mma_bf16(sre[nt], qiL, bIH);
                    // im = QiKr - QrKi
                    mma_bf16(sim[nt], qiH, bRH);
                    mma_bf16(sim[nt], qiH, bRL);
                    mma_bf16(sim[nt], qiL, bRH);
                    mma_bf16(sim[nt], qrH, nIH);
                    mma_bf16(sim[nt], qrH, nIL);
                    mma_bf16(sim[nt], qrL, nIH);
                }
            }
        }

        // ---- online softmax + weight fragments ----
        float cx0 = -1e30f, cx1 = -1e30f;
#pragma unroll
        for (int nt = 0; nt < 8; nt++) {
#pragma unroll
            for (int q = 0; q < 4; q++) { sre[nt][q] *= scale; sim[nt][q] *= scale; }
            cx0 = fmaxf(cx0, fmaxf(sre[nt][0], sre[nt][1]));
            cx1 = fmaxf(cx1, fmaxf(sre[nt][2], sre[nt][3]));
        }
        cx0 = fmaxf(cx0, __shfl_xor_sync(0xffffffffu, cx0, 1));
        cx0 = fmaxf(cx0, __shfl_xor_sync(0xffffffffu, cx0, 2));
        cx1 = fmaxf(cx1, __shfl_xor_sync(0xffffffffu, cx1, 1));
        cx1 = fmaxf(cx1, __shfl_xor_sync(0xffffffffu, cx1, 2));

        float nm0 = fmaxf(m0, cx0), nm1 = fmaxf(m1, cx1);
        float al0 = __expf(m0 - nm0), al1 = __expf(m1 - nm1);
        m0 = nm0; m1 = nm1;

        float rs0 = 0.f, rs1 = 0.f;
#pragma unroll
        for (int nt = 0; nt < 8; nt++) {
            float p0 = __expf(sre[nt][0] - nm0);
            float p1 = __expf(sre[nt][1] - nm0);
            float p2 = __expf(sre[nt][2] - nm1);
            float p3 = __expf(sre[nt][3] - nm1);
            rs0 += p0 + p1; rs1 += p2 + p3;
            float sn, cs;
            __sincosf(sim[nt][0], &sn, &cs); sre[nt][0] = p0 * cs; sim[nt][0] = p0 * sn;
            __sincosf(sim[nt][1], &sn, &cs); sre[nt][1] = p1 * cs; sim[nt][1] = p1 * sn;
            __sincosf(sim[nt][2], &sn, &cs); sre[nt][2] = p2 * cs; sim[nt][2] = p2 * sn;
            __sincosf(sim[nt][3], &sn, &cs); sre[nt][3] = p3 * cs; sim[nt][3] = p3 * sn;
        }
        rs0 += __shfl_xor_sync(0xffffffffu, rs0, 1);
        rs0 += __shfl_xor_sync(0xffffffffu, rs0, 2);
        rs1 += __shfl_xor_sync(0xffffffffu, rs1, 1);
        rs1 += __shfl_xor_sync(0xffffffffu, rs1, 2);
        l0 = l0 * al0 + rs0;
        l1 = l1 * al1 + rs1;
#pragma unroll
        for (int nt = 0; nt < 8; nt++) {
            or_[nt][0] *= al0; or_[nt][1] *= al0; or_[nt][2] *= al1; or_[nt][3] *= al1;
            oi_[nt][0] *= al0; oi_[nt][1] *= al0; oi_[nt][2] *= al1; oi_[nt][3] *= al1;
        }

        // W C-frags -> A-frags in registers (hi/lo split)
        uint32_t wcH[4][4], wcL[4][4], wsH[4][4], wsL[4][4];
#pragma unroll
        for (int t = 0; t < 4; t++)
#pragma unroll
            for (int r = 0; r < 4; r++) {
                int nt = 2 * t + (r >> 1);
                int e = (r & 1) * 2;
                __nv_bfloat16 h0, lo0, h1, lo1;
                bsplit(sre[nt][e], h0, lo0); bsplit(sre[nt][e + 1], h1, lo1);
                wcH[t][r] = packbf2(h0, h1); wcL[t][r] = packbf2(lo0, lo1);
                bsplit(sim[nt][e], h0, lo0); bsplit(sim[nt][e + 1], h1, lo1);
                wsH[t][r] = packbf2(h0, h1); wsL[t][r] = packbf2(lo0, lo1);
            }

        // ---- PV: out_r += Wc*Vr - Ws*Vi ; out_i += Wc*Vi + Ws*Vr ----
#pragma unroll
        for (int ks = 0; ks < 4; ks++) {
#pragma unroll
            for (int nt16 = 0; nt16 < 4; nt16++) {
                uint32_t vb = stg + (uint32_t)(nt16 * 16 + krow) * AP + ks * 32 + koff;
                uint32_t vrH[4], vrL[4], viH[4], viL[4];
                ldsm_x4(vrH, vb + 4 * KCOMP);
                ldsm_x4(vrL, vb + 5 * KCOMP);
                ldsm_x4(viH, vb + 6 * KCOMP);
                ldsm_x4(viL, vb + 7 * KCOMP);
#pragma unroll
                for (int hf = 0; hf < 2; hf++) {
                    int nt = nt16 * 2 + hf;
                    const uint32_t* bRH = vrH + hf * 2;
                    const uint32_t* bRL = vrL + hf * 2;
                    const uint32_t* bIH = viH + hf * 2;
                    const uint32_t* bIL = viL + hf * 2;
                    uint32_t nIH[2] = {bIH[0] ^ SGNX2, bIH[1] ^ SGNX2};
                    uint32_t nIL[2] = {bIL[0] ^ SGNX2, bIL[1] ^ SGNX2};
                    mma_bf16(or_[nt], wcH[ks], bRH);
                    mma_bf16(or_[nt], wcH[ks], bRL);
                    mma_bf16(or_[nt], wcL[ks], bRH);
                    mma_bf16(or_[nt], wsH[ks], nIH);
                    mma_bf16(or_[nt], wsH[ks], nIL);
                    mma_bf16(or_[nt], wsL[ks], nIH);
                    mma_bf16(oi_[nt], wcH[ks], bIH);
                    mma_bf16(oi_[nt], wcH[ks], bIL);
                    mma_bf16(oi_[nt], wcL[ks], bIH);
                    mma_bf16(oi_[nt], wsH[ks], bRH);
                    mma_bf16(oi_[nt], wsH[ks], bRL);
                    mma_bf16(oi_[nt], wsL[ks], bRH);
                }
            }
        }
        __syncthreads();
    }

    // ---- epilogue ----
    int b = bh >> 4;
    int h = bh & 15;
    float inv0 = 1.0f / l0, inv1 = 1.0f / l1;
    int qr0 = q0 + w * 16 + grp;
#pragma unroll
    for (int nt = 0; nt < 8; nt++) {
        int col = h * 64 + nt * 8 + tq * 2;
        size_t r0 = (size_t)(b * SEQ + qr0) * D_MODEL + col;
        size_t r1 = (size_t)(b * SEQ + qr0 + 8) * D_MODEL + col;
        *(float2*)(g_att_r + r0) = {or_[nt][0] * inv0, or_[nt][1] * inv0};
        *(float2*)(g_att_r + r1) = {or_[nt][2] * inv1, or_[nt][3] * inv1};
        *(float2*)(g_att_i + r0) = {oi_[nt][0] * inv0, oi_[nt][1] * inv0};
        *(float2*)(g_att_i + r1) = {oi_[nt][2] * inv1, oi_[nt][3] * inv1};
    }
}

// ---------------- launch ----------------
static inline void launch_split(const float* src, __nv_bfloat16* hi, __nv_bfloat16* lo, int n) {
    int n4 = n / 4;
    split_kernel<<<(n4 + 255) / 256, 256>>>(src, hi, lo, n4);
}

extern "C" void kernel_launch(void* const* d_in, const int* in_sizes, int n_in,
                              void* d_out, int out_size) {
    (void)in_sizes; (void)n_in; (void)out_size;
    const float* x_re    = (const float*)d_in[0];
    const float* x_im    = (const float*)d_in[1];
    const float* wqkv_re = (const float*)d_in[2];
    const float* wqkv_im = (const float*)d_in[3];
    const float* wo_re   = (const float*)d_in[4];
    const float* wo_im   = (const float*)d_in[5];
    float* out = (float*)d_out;

    float *p_qkv_r, *p_qkv_i, *p_att_r, *p_att_i;
    cudaGetSymbolAddress((void**)&p_qkv_r, g_qkv_r);
    cudaGetSymbolAddress((void**)&p_qkv_i, g_qkv_i);
    cudaGetSymbolAddress((void**)&p_att_r, g_att_r);
    cudaGetSymbolAddress((void**)&p_att_i, g_att_i);

    __nv_bfloat16 *xrH, *xrL, *xiH, *xiL, *wqrH, *wqrL, *wqiH, *wqiL;
    __nv_bfloat16 *worH, *worL, *woiH, *woiL, *arH, *arL, *aiH, *aiL;
    cudaGetSymbolAddress((void**)&xrH, g_xrH);   cudaGetSymbolAddress((void**)&xrL, g_xrL);
    cudaGetSymbolAddress((void**)&xiH, g_xiH);   cudaGetSymbolAddress((void**)&xiL, g_xiL);
    cudaGetSymbolAddress((void**)&wqrH, g_wqrH); cudaGetSymbolAddress((void**)&wqrL, g_wqrL);
    cudaGetSymbolAddress((void**)&wqiH, g_wqiH); cudaGetSymbolAddress((void**)&wqiL, g_wqiL);
    cudaGetSymbolAddress((void**)&worH, g_worH); cudaGetSymbolAddress((void**)&worL, g_worL);
    cudaGetSymbolAddress((void**)&woiH, g_woiH); cudaGetSymbolAddress((void**)&woiL, g_woiL);
    cudaGetSymbolAddress((void**)&arH, g_arH);   cudaGetSymbolAddress((void**)&arL, g_arL);
    cudaGetSymbolAddress((void**)&aiH, g_aiH);   cudaGetSymbolAddress((void**)&aiL, g_aiL);

    cudaFuncSetAttribute(cgemm_tc_kernel,
                         cudaFuncAttributeMaxDynamicSharedMemorySize, G_SMEM);
    cudaFuncSetAttribute(attn_tc_kernel,
                         cudaFuncAttributeMaxDynamicSharedMemorySize, A_SMEM);

    // 1. rope table
    rope_table_kernel<<<(SEQ * D_HEAD + 255) / 256, 256>>>();

    // 2. bf16 splits of inputs + weights
    launch_split(x_re, xrH, xrL, XN);
    launch_split(x_im, xiH, xiL, XN);
    launch_split(wqkv_re, wqrH, wqrL, WQN);
    launch_split(wqkv_im, wqiH, wqiL, WQN);
    launch_split(wo_re, worH, worL, WON);
    launch_split(wo_im, woiH, woiL, WON);

    // 3. QKV projection (tensor cores)
    {
        dim3 grid(QKV_N / GBN, M_TOK / GBM);
        cgemm_tc_kernel<<<grid, 256, G_SMEM>>>(
            xrH, xrL, xiH, xiL, wqrH, wqrL, wqiH, wqiL,
            p_qkv_r, p_qkv_i, QKV_N, D_MODEL);
    }

    // 4. rope apply + head split + bf16 emit
    rope_apply_kernel<<<(QS + 255) / 256, 256>>>();

    // 5. tensor-core flash attention
    {
        dim3 grid(SEQ / 128, BHN);
        attn_tc_kernel<<<grid, 256, A_SMEM>>>();
    }

    // 6. split attention output, output projection (tensor cores) -> d_out
    launch_split(p_att_r, arH, arL, XN);
    launch_split(p_att_i, aiH, aiL, XN);
    {
        dim3 grid(D_MODEL / GBN, M_TOK / GBM);
        cgemm_tc_kernel<<<grid, 256, G_SMEM>>>(
            arH, arL, aiH, aiL, worH, worL, woiH, woiL,
            out, out + (size_t)M_TOK * D_MODEL, D_MODEL, D_MODEL);
    }
}